// round 5
// baseline (speedup 1.0000x reference)
#include <cuda_runtime.h>

// ===================== problem constants =====================
#define B_      32
#define N_      3137
#define C_      768
#define H_      12
#define D_      64
#define SCALE_  0.125f          // 1/sqrt(64)
#define C4_     192             // C_/4

// split-KV config
#define SPLITS  23
#define CHUNK   137             // ceil(3137/23)
#define TT_     28              // tokens per tile (double-buffered)
#define XS_STRIDE 772           // 768 + 4 pad floats (odd float4 stride -> conflict-free)
#define K2_THREADS 512          // 16 warps: 4 head-groups x 4 c-quarters

typedef unsigned long long u64;
struct __align__(16) U64x2 { u64 a, b; };

// ===================== device scratch =====================
__device__ float g_qs[B_][C_];                       // SCALE*(q_w x0 + q_b)
__device__ float g_s [B_][H_][C_];                   // s vectors
__device__ float g_m [B_][SPLITS][H_];
__device__ float g_l [B_][SPLITS][H_];
__device__ float g_y [B_][SPLITS][H_][C_];           // unnormalized partial y
__device__ float g_cls[B_][C_];                      // v-projected cls embedding

__device__ __forceinline__ float dot4(float4 a, float4 b) {
    return a.x*b.x + a.y*b.y + a.z*b.z + a.w*b.w;
}

// packed dual-fp32 helpers (sm_100a f32x2 pipe)
__device__ __forceinline__ u64 fma2(u64 a, u64 b, u64 c) {
    u64 d;
    asm("fma.rn.f32x2 %0, %1, %2, %3;" : "=l"(d) : "l"(a), "l"(b), "l"(c));
    return d;
}
__device__ __forceinline__ u64 mul2(u64 a, u64 b) {
    u64 d;
    asm("mul.rn.f32x2 %0, %1, %2;" : "=l"(d) : "l"(a), "l"(b));
    return d;
}
__device__ __forceinline__ u64 pack2(float p) {
    u64 d; unsigned u = __float_as_uint(p);
    asm("mov.b64 %0, {%1, %1};" : "=l"(d) : "r"(u));
    return d;
}
__device__ __forceinline__ float hsum2(u64 v) {
    float lo = __uint_as_float((unsigned)(v & 0xffffffffull));
    float hi = __uint_as_float((unsigned)(v >> 32));
    return lo + hi;
}

// cp.async 16B (LDGSTS)
__device__ __forceinline__ void cpa16(void* smem_dst, const void* gsrc) {
    unsigned saddr = (unsigned)__cvta_generic_to_shared(smem_dst);
    asm volatile("cp.async.cg.shared.global [%0], [%1], 16;"
                 :: "r"(saddr), "l"(gsrc) : "memory");
}

// ===================== K1a: q vectors (split into 2 launches) =====================
__global__ void k_q(const float* __restrict__ x,
                    const float* __restrict__ q_w,
                    const float* __restrict__ q_b, int p0) {
    __shared__ float x0[C_];
    int p = p0 + blockIdx.x, b = blockIdx.y, tid = threadIdx.x;
    for (int i = tid; i < C_; i += 256)
        x0[i] = x[(size_t)b * N_ * C_ + i];
    __syncthreads();
    int w = tid >> 5, lane = tid & 31;
    const float4* x04 = (const float4*)x0;
    for (int oo = w; oo < 192; oo += 8) {
        int o = p * 192 + oo;
        const float4* qr = (const float4*)(q_w + (size_t)o * C_);
        float s = 0.f;
        #pragma unroll
        for (int k = 0; k < 6; k++)
            s += dot4(qr[lane + 32*k], x04[lane + 32*k]);
        #pragma unroll
        for (int off = 16; off; off >>= 1)
            s += __shfl_xor_sync(0xffffffffu, s, off);
        if (lane == 0) g_qs[b][o] = SCALE_ * (s + q_b[o]);
    }
}

// ===================== K1b: s vectors =====================
__global__ void k_s(const float* __restrict__ kv_w) {
    __shared__ float qs[C_];
    int p = blockIdx.x, b = blockIdx.y, tid = threadIdx.x;
    for (int i = tid; i < C_; i += 256) qs[i] = g_qs[b][i];
    __syncthreads();
    float* gs = &g_s[b][0][0];
    int lo = p * 1152, hi = lo + 1152;
    for (int idx = lo + tid; idx < hi; idx += 256) {
        int h = idx / C_, c = idx - h * C_;
        const float* kr = kv_w + (size_t)(h * 64) * C_ + c;
        const float* qh = qs + h * 64;
        float acc = 0.f;
        #pragma unroll 8
        for (int d = 0; d < 64; d++)
            acc = fmaf(kr[(size_t)d * C_], qh[d], acc);
        gs[idx] = acc;
    }
}

// ===================== K2: main streaming attention =====================
// grid (SPLITS, B_), 512 threads, ~220KB smem, cp.async double-buffered.
// Warp role: hg = w>>2 (heads 3hg..3hg+2), cs = w&3 (48-float4 quarter).
__device__ __forceinline__ void issue_tile(const float* __restrict__ x,
                                           float* xsb, int b, int t0,
                                           int TTl, int tid) {
    const float4* xg = (const float4*)x + ((size_t)b * N_ + t0) * C4_;
    #pragma unroll
    for (int k = 0; k < 11; k++) {
        int f = tid + k * K2_THREADS;
        if (f < TT_ * C4_) {
            int t = f / C4_, c4 = f - t * C4_;
            if (t < TTl)
                cpa16(xsb + t * XS_STRIDE + 4 * c4, xg + (size_t)t * C4_ + c4);
        }
    }
    asm volatile("cp.async.commit_group;" ::: "memory");
}

__global__ __launch_bounds__(K2_THREADS, 1)
void k_attn(const float* __restrict__ x) {
    extern __shared__ float sm[];
    float* xs   = sm;                                 // 2 * 28 * 772
    float* s_sm = sm + 2 * TT_ * XS_STRIDE;           // 9216
    float* pr   = s_sm + H_ * C_;                     // 16 warps x 32 x float4
    float* p_sm = pr + 2048;                          // [32][12]
    float* m_sm = p_sm + 384;                         // [12]
    float* l_sm = m_sm + H_;                          // [12]
    float* a_sm = l_sm + H_;                          // [12]

    int sp = blockIdx.x, b = blockIdx.y;
    int tid = threadIdx.x, w = tid >> 5, lane = tid & 31;
    int n0 = sp * CHUNK;
    int n1 = min(N_, n0 + CHUNK);
    int nT = (n1 - n0 + TT_ - 1) / TT_;

    // preload tile 0 into buffer 0
    issue_tile(x, xs, b, n0, min(TT_, n1 - n0), tid);

    // load s into smem
    {
        const float4* gs4 = (const float4*)&g_s[b][0][0];
        float4* s4 = (float4*)s_sm;
        for (int i = tid; i < H_ * C4_; i += K2_THREADS) s4[i] = gs4[i];
    }
    if (tid < H_) { m_sm[tid] = -1e30f; l_sm[tid] = 0.f; }

    int hg = w >> 2, cs = w & 3;          // heads 3hg..3hg+2, quarter cs
    int hgp = w / 3, r = w - 3 * hgp;     // softmax role (valid for w<12)

    u64 y0[3], y1[3], y2[3];
    #pragma unroll
    for (int i = 0; i < 3; i++) { y0[i] = 0ull; y1[i] = 0ull; y2[i] = 0ull; }

    for (int it = 0; it < nT; it++) {
        int t0 = n0 + it * TT_;
        int TTl = min(TT_, n1 - t0);
        float* xsb = xs + (it & 1) * (TT_ * XS_STRIDE);

        asm volatile("cp.async.wait_group 0;" ::: "memory");
        __syncthreads();   // tile `it` resident; all warps done with iter it-1

        // issue next tile: target buffer was fully consumed in iter it-1
        if (it + 1 < nT)
            issue_tile(x, xs + ((it + 1) & 1) * (TT_ * XS_STRIDE),
                       b, t0 + TT_, min(TT_, n1 - t0 - TT_), tid);

        // ---- phase A: partial logits (3 heads x quarter), lane = token ----
        {
            u64 a0 = 0ull, a1 = 0ull, a2 = 0ull;
            const char* xp = (const char*)(xsb + lane * XS_STRIDE) + 16 * (48 * cs);
            const char* sb = (const char*)(s_sm + 3 * hg * C_) + 16 * (48 * cs);
            #pragma unroll 4
            for (int c4 = 0; c4 < 48; c4++) {
                U64x2 xv = *(const U64x2*)xp;
                U64x2 s0 = *(const U64x2*)(sb);
                U64x2 s1 = *(const U64x2*)(sb + (size_t)(C_ * 4));
                U64x2 s2 = *(const U64x2*)(sb + (size_t)(2 * C_ * 4));
                a0 = fma2(xv.a, s0.a, a0); a0 = fma2(xv.b, s0.b, a0);
                a1 = fma2(xv.a, s1.a, a1); a1 = fma2(xv.b, s1.b, a1);
                a2 = fma2(xv.a, s2.a, a2); a2 = fma2(xv.b, s2.b, a2);
                xp += 16; sb += 16;
            }
            ((float4*)pr)[w * 32 + lane] =
                make_float4(hsum2(a0), hsum2(a1), hsum2(a2), 0.f);
        }
        __syncthreads();

        // ---- softmax (with quarter-reduce folded in): warp w = head w ----
        if (w < H_) {
            float v = -1e30f;
            if (lane < TTl) {
                v = pr[((hgp * 4 + 0) * 32 + lane) * 4 + r]
                  + pr[((hgp * 4 + 1) * 32 + lane) * 4 + r]
                  + pr[((hgp * 4 + 2) * 32 + lane) * 4 + r]
                  + pr[((hgp * 4 + 3) * 32 + lane) * 4 + r];
            }
            float mt = v;
            #pragma unroll
            for (int off = 16; off; off >>= 1)
                mt = fmaxf(mt, __shfl_xor_sync(0xffffffffu, mt, off));
            float mo = m_sm[w];
            float mn = fmaxf(mo, mt);
            float pv = (lane < TTl) ? __expf(v - mn) : 0.f;
            float lt = pv;
            #pragma unroll
            for (int off = 16; off; off >>= 1)
                lt += __shfl_xor_sync(0xffffffffu, lt, off);
            p_sm[lane * 12 + w] = pv;
            if (lane == 0) {
                float al = __expf(mo - mn);
                l_sm[w] = al * l_sm[w] + lt;
                m_sm[w] = mn;
                a_sm[w] = al;
            }
        }
        __syncthreads();

        // ---- phase B: y[h] = alpha*y[h] + sum_t p[t,h]*x[t] ----
        {
            u64 al0 = pack2(a_sm[3 * hg + 0]);
            u64 al1 = pack2(a_sm[3 * hg + 1]);
            u64 al2 = pack2(a_sm[3 * hg + 2]);
            #pragma unroll
            for (int i = 0; i < 3; i++) {
                y0[i] = mul2(y0[i], al0);
                y1[i] = mul2(y1[i], al1);
                y2[i] = mul2(y2[i], al2);
            }
            float pv0 = p_sm[lane * 12 + 3 * hg + 0];
            float pv1 = p_sm[lane * 12 + 3 * hg + 1];
            float pv2 = p_sm[lane * 12 + 3 * hg + 2];
            const char* xbase = (const char*)xsb + 8 * (cs * 96 + lane);
            #pragma unroll 4
            for (int t = 0; t < TT_; t++) {   // p==0 beyond TTl
                u64 p0 = pack2(__shfl_sync(0xffffffffu, pv0, t));
                u64 p1 = pack2(__shfl_sync(0xffffffffu, pv1, t));
                u64 p2 = pack2(__shfl_sync(0xffffffffu, pv2, t));
                const char* xr = xbase + (size_t)t * (XS_STRIDE * 4);
                #pragma unroll
                for (int i = 0; i < 3; i++) {
                    u64 xv = *(const u64*)(xr + 8 * (32 * i));
                    y0[i] = fma2(p0, xv, y0[i]);
                    y1[i] = fma2(p1, xv, y1[i]);
                    y2[i] = fma2(p2, xv, y2[i]);
                }
            }
        }
        // no trailing sync: next iter's top sync fences buffer reuse
    }
    __syncthreads();

    if (tid < H_) {
        g_m[b][sp][tid] = m_sm[tid];
        g_l[b][sp][tid] = l_sm[tid];
    }
    {
        u64* gy0 = (u64*)&g_y[b][sp][3 * hg + 0][0];
        u64* gy1 = (u64*)&g_y[b][sp][3 * hg + 1][0];
        u64* gy2 = (u64*)&g_y[b][sp][3 * hg + 2][0];
        int cb = cs * 96 + lane;
        #pragma unroll
        for (int i = 0; i < 3; i++) {
            gy0[cb + 32 * i] = y0[i];
            gy1[cb + 32 * i] = y1[i];
            gy2[cb + 32 * i] = y2[i];
        }
    }
}

// ===================== K3: combine splits + V-proj (fused) =====================
// grid (H_, B_), 256 threads.
__global__ void k_cc(const float* __restrict__ kv_w,
                     const float* __restrict__ kv_b) {
    int h = blockIdx.x, b = blockIdx.y, tid = threadIdx.x;
    int w = tid >> 5, lane = tid & 31;
    __shared__ float ws[SPLITS];
    __shared__ float linv_s;
    __shared__ float y_s[C_];

    if (tid < 32) {
        float m = (lane < SPLITS) ? g_m[b][lane][h] : -1e30f;
        float mg = m;
        #pragma unroll
        for (int off = 16; off; off >>= 1)
            mg = fmaxf(mg, __shfl_xor_sync(0xffffffffu, mg, off));
        float e = (lane < SPLITS) ? __expf(m - mg) : 0.f;
        float le = (lane < SPLITS) ? g_l[b][lane][h] * e : 0.f;
        #pragma unroll
        for (int off = 16; off; off >>= 1)
            le += __shfl_xor_sync(0xffffffffu, le, off);
        if (lane < SPLITS) ws[lane] = e;
        if (lane == 0) linv_s = 1.f / le;
    }
    __syncthreads();

    if (tid < C4_) {
        float4 acc = make_float4(0.f, 0.f, 0.f, 0.f);
        #pragma unroll
        for (int s = 0; s < SPLITS; s++) {
            float4 v = ((const float4*)&g_y[b][s][h][0])[tid];
            float wv = ws[s];
            acc.x = fmaf(wv, v.x, acc.x);
            acc.y = fmaf(wv, v.y, acc.y);
            acc.z = fmaf(wv, v.z, acc.z);
            acc.w = fmaf(wv, v.w, acc.w);
        }
        float li = linv_s;
        ((float4*)y_s)[tid] =
            make_float4(acc.x * li, acc.y * li, acc.z * li, acc.w * li);
    }
    __syncthreads();

    const float4* y4 = (const float4*)y_s;
    for (int oo = w; oo < 64; oo += 8) {
        int o = h * 64 + oo;
        const float4* kr = (const float4*)(kv_w + (size_t)(C_ + o) * C_);
        float s = 0.f;
        #pragma unroll
        for (int k = 0; k < 6; k++)
            s += dot4(kr[lane + 32*k], y4[lane + 32*k]);
        #pragma unroll
        for (int off = 16; off; off >>= 1)
            s += __shfl_xor_sync(0xffffffffu, s, off);
        if (lane == 0) g_cls[b][o] = s + kv_b[C_ + o];
    }
}

// ===================== K4: out = W_p cls + b_p =====================
__global__ void k_proj(const float* __restrict__ proj_w,
                       const float* __restrict__ proj_b,
                       float* __restrict__ out) {
    int xblk = blockIdx.x, b = blockIdx.y, tid = threadIdx.x;
    int w = tid >> 5, lane = tid & 31;
    __shared__ float c_s[C_];
    for (int i = tid; i < C_; i += 256) c_s[i] = g_cls[b][i];
    __syncthreads();
    const float4* c4 = (const float4*)c_s;
    for (int oo = w; oo < 64; oo += 8) {
        int o = xblk * 64 + oo;
        const float4* prw = (const float4*)(proj_w + (size_t)o * C_);
        float s = 0.f;
        #pragma unroll
        for (int k = 0; k < 6; k++)
            s += dot4(prw[lane + 32*k], c4[lane + 32*k]);
        #pragma unroll
        for (int off = 16; off; off >>= 1)
            s += __shfl_xor_sync(0xffffffffu, s, off);
        if (lane == 0) out[b * C_ + o] = s + proj_b[o];
    }
}

// ===================== launch =====================
extern "C" void kernel_launch(void* const* d_in, const int* in_sizes, int n_in,
                              void* d_out, int out_size) {
    const float* x      = (const float*)d_in[0];
    const float* kv_w   = (const float*)d_in[1];
    const float* kv_b   = (const float*)d_in[2];
    const float* q_w    = (const float*)d_in[3];
    const float* q_b    = (const float*)d_in[4];
    const float* proj_w = (const float*)d_in[5];
    const float* proj_b = (const float*)d_in[6];
    float* out = (float*)d_out;

    size_t smem = (size_t)(2 * TT_ * XS_STRIDE + H_ * C_ + 2048 + 384 + 3 * H_)
                  * sizeof(float);   // 219,664 B
    cudaFuncSetAttribute(k_attn, cudaFuncAttributeMaxDynamicSharedMemorySize,
                         (int)smem);

    k_q    <<<dim3(2, B_), 256>>>(x, q_w, q_b, 0);   // launch 1
    k_q    <<<dim3(2, B_), 256>>>(x, q_w, q_b, 2);   // launch 2
    k_s    <<<dim3(8, B_), 256>>>(kv_w);             // launch 3
    k_attn <<<dim3(SPLITS, B_), K2_THREADS, smem>>>(x);  // launch 4 (ncu target)
    k_cc   <<<dim3(H_, B_), 256>>>(kv_w, kv_b);      // launch 5
    k_proj <<<dim3(H_, B_), 256>>>(proj_w, proj_b, out); // launch 6
}

// round 7
// speedup vs baseline: 1.2743x; 1.2743x over previous
#include <cuda_runtime.h>

// ===================== problem constants =====================
#define B_      32
#define N_      3137
#define C_      768
#define H_      12
#define D_      64
#define SCALE_  0.125f          // 1/sqrt(64)
#define C4_     192             // C_/4

// split-KV config
#define SPLITS  23
#define CHUNK   137             // ceil(3137/23)
#define TT_     28              // tokens per tile (double-buffered)
#define XS_STRIDE 772           // 768+4 pad floats (stride 4 mod 32 banks -> conflict-free)
#define K2_THREADS 512          // 16 warps

typedef unsigned long long u64;
struct __align__(16) U64x2 { u64 a, b; };

// ===================== device scratch =====================
__device__ float g_s [B_][H_][C_];                   // s vectors
__device__ float g_m [B_][SPLITS][H_];
__device__ float g_l [B_][SPLITS][H_];
__device__ float g_y [B_][SPLITS][H_][C_];           // unnormalized partial y
__device__ float g_cls[B_][C_];                      // v-projected cls embedding

__device__ __forceinline__ float dot4(float4 a, float4 b) {
    return a.x*b.x + a.y*b.y + a.z*b.z + a.w*b.w;
}

// packed dual-fp32 helpers
__device__ __forceinline__ u64 fma2(u64 a, u64 b, u64 c) {
    u64 d;
    asm("fma.rn.f32x2 %0, %1, %2, %3;" : "=l"(d) : "l"(a), "l"(b), "l"(c));
    return d;
}
__device__ __forceinline__ u64 mul2(u64 a, u64 b) {
    u64 d;
    asm("mul.rn.f32x2 %0, %1, %2;" : "=l"(d) : "l"(a), "l"(b));
    return d;
}
__device__ __forceinline__ u64 pack2(float p) {
    u64 d; unsigned u = __float_as_uint(p);
    asm("mov.b64 %0, {%1, %1};" : "=l"(d) : "r"(u));
    return d;
}
__device__ __forceinline__ float hsum2(u64 v) {
    float lo = __uint_as_float((unsigned)(v & 0xffffffffull));
    float hi = __uint_as_float((unsigned)(v >> 32));
    return lo + hi;
}

// cp.async 16B (LDGSTS)
__device__ __forceinline__ void cpa16(void* smem_dst, const void* gsrc) {
    unsigned saddr = (unsigned)__cvta_generic_to_shared(smem_dst);
    asm volatile("cp.async.cg.shared.global [%0], [%1], 16;"
                 :: "r"(saddr), "l"(gsrc) : "memory");
}

// ===================== K1: fused q + s, one block per (b, h) =====================
// q[d] = SCALE*(q_b[64h+d] + q_w[64h+d]·x[b,0,:]),  s[c] = sum_d kv_w[64h+d][c]*q[d]
__global__ void k_qs(const float* __restrict__ x,
                     const float* __restrict__ q_w,
                     const float* __restrict__ q_b,
                     const float* __restrict__ kv_w) {
    __shared__ float x0[C_];
    __shared__ float qh[D_];
    int h = blockIdx.x, b = blockIdx.y, tid = threadIdx.x;
    int w = tid >> 5, lane = tid & 31;
    for (int i = tid; i < C_; i += 256)
        x0[i] = x[(size_t)b * N_ * C_ + i];
    __syncthreads();
    const float4* x04 = (const float4*)x0;
    for (int oo = w; oo < D_; oo += 8) {
        int o = h * D_ + oo;
        const float4* qr = (const float4*)(q_w + (size_t)o * C_);
        float s = 0.f;
        #pragma unroll
        for (int k = 0; k < 6; k++)
            s += dot4(qr[lane + 32*k], x04[lane + 32*k]);
        #pragma unroll
        for (int off = 16; off; off >>= 1)
            s += __shfl_xor_sync(0xffffffffu, s, off);
        if (lane == 0) qh[oo] = SCALE_ * (s + q_b[o]);
    }
    __syncthreads();
    // s: thread owns columns tid, tid+256, tid+512
    float a0 = 0.f, a1 = 0.f, a2 = 0.f;
    const float* kr = kv_w + (size_t)(h * D_) * C_;
    #pragma unroll 4
    for (int d = 0; d < D_; d++) {
        float qd = qh[d];
        a0 = fmaf(kr[tid      ], qd, a0);
        a1 = fmaf(kr[tid + 256], qd, a1);
        a2 = fmaf(kr[tid + 512], qd, a2);
        kr += C_;
    }
    g_s[b][h][tid      ] = a0;
    g_s[b][h][tid + 256] = a1;
    g_s[b][h][tid + 512] = a2;
}

// ===================== K2: main streaming attention =====================
// grid (SPLITS, B_), 512 threads, ~224KB smem, cp.async double-buffered.
// Phase A: 16 warps = 8 c-slices (24 float4) x 2 head-halves (6 heads); lane=token.
// Phase B: 12 warps = 6 c-sixths (64 u64)   x 2 head-halves (6 heads); lane=u64 col.
__device__ __forceinline__ void issue_tile(const float* __restrict__ x,
                                           float* xsb, int b, int t0,
                                           int TTl, int tid) {
    const float4* xg = (const float4*)x + ((size_t)b * N_ + t0) * C4_;
    #pragma unroll
    for (int k = 0; k < 11; k++) {
        int f = tid + k * K2_THREADS;
        if (f < TT_ * C4_) {
            int t = f / C4_, c4 = f - t * C4_;
            if (t < TTl)
                cpa16(xsb + t * XS_STRIDE + 4 * c4, xg + (size_t)t * C4_ + c4);
        }
    }
    asm volatile("cp.async.commit_group;" ::: "memory");
}

__global__ __launch_bounds__(K2_THREADS, 1)
void k_attn(const float* __restrict__ x) {
    extern __shared__ float sm[];
    float* xs   = sm;                                 // 2 * 28 * 772 = 43232
    float* s_sm = sm + 2 * TT_ * XS_STRIDE;           // 9216
    float* pr   = s_sm + H_ * C_;                     // [12][8][32] = 3072
    float* p_sm = pr + H_ * 8 * 32;                   // [12][32] transposed
    float* m_sm = p_sm + H_ * 32;                     // [12]
    float* l_sm = m_sm + H_;                          // [12]
    float* a_sm = l_sm + H_;                          // [12]

    int sp = blockIdx.x, b = blockIdx.y;
    int tid = threadIdx.x, w = tid >> 5, lane = tid & 31;
    int n0 = sp * CHUNK;
    int n1 = min(N_, n0 + CHUNK);
    int nT = (n1 - n0 + TT_ - 1) / TT_;

    // preload tile 0 into buffer 0
    issue_tile(x, xs, b, n0, min(TT_, n1 - n0), tid);

    // load s into smem
    {
        const float4* gs4 = (const float4*)&g_s[b][0][0];
        float4* s4 = (float4*)s_sm;
        for (int i = tid; i < H_ * C4_; i += K2_THREADS) s4[i] = gs4[i];
    }
    if (tid < H_) { m_sm[tid] = -1e30f; l_sm[tid] = 0.f; }

    // phase A roles
    int hhA = w & 1, sc = w >> 1;            // heads 6*hhA.., c4 slice [24sc, 24sc+24)
    // phase B roles (warps 0..11)
    int hhB = w % 2, cx = w >> 1;            // heads 6*hhB.., u64 cols [64cx, 64cx+64)

    u64 y[6][2];
    #pragma unroll
    for (int j = 0; j < 6; j++) { y[j][0] = 0ull; y[j][1] = 0ull; }

    for (int it = 0; it < nT; it++) {
        int t0 = n0 + it * TT_;
        int TTl = min(TT_, n1 - t0);
        float* xsb = xs + (it & 1) * (TT_ * XS_STRIDE);

        asm volatile("cp.async.wait_group 0;" ::: "memory");
        __syncthreads();   // tile resident; all warps finished iter it-1

        // issue next tile: target buffer fully consumed in iter it-1
        if (it + 1 < nT)
            issue_tile(x, xs + ((it + 1) & 1) * (TT_ * XS_STRIDE),
                       b, t0 + TT_, min(TT_, n1 - t0 - TT_), tid);

        // ---- phase A: partial logits, lane = token, 6 heads x 24 c4 ----
        {
            u64 acc[6] = {0ull, 0ull, 0ull, 0ull, 0ull, 0ull};
            const char* xp = (const char*)(xsb + lane * XS_STRIDE) + 16 * (24 * sc);
            const char* sb = (const char*)(s_sm + 6 * hhA * C_) + 16 * (24 * sc);
            #pragma unroll 4
            for (int c4 = 0; c4 < 24; c4++) {
                U64x2 xv = *(const U64x2*)xp;
                #pragma unroll
                for (int j = 0; j < 6; j++) {
                    U64x2 sv = *(const U64x2*)(sb + (size_t)j * (C_ * 4));
                    acc[j] = fma2(xv.a, sv.a, acc[j]);
                    acc[j] = fma2(xv.b, sv.b, acc[j]);
                }
                xp += 16; sb += 16;
            }
            #pragma unroll
            for (int j = 0; j < 6; j++)
                pr[((6 * hhA + j) * 8 + sc) * 32 + lane] = hsum2(acc[j]);
        }
        __syncthreads();

        // ---- softmax (folds slice-reduce): warp w = head w ----
        if (w < H_) {
            float v = -1e30f;
            if (lane < TTl) {
                v = 0.f;
                #pragma unroll
                for (int s8 = 0; s8 < 8; s8++)
                    v += pr[(w * 8 + s8) * 32 + lane];
            }
            float mt = v;
            #pragma unroll
            for (int off = 16; off; off >>= 1)
                mt = fmaxf(mt, __shfl_xor_sync(0xffffffffu, mt, off));
            float mo = m_sm[w];
            float mn = fmaxf(mo, mt);
            float pv = (lane < TTl) ? __expf(v - mn) : 0.f;
            float lt = pv;
            #pragma unroll
            for (int off = 16; off; off >>= 1)
                lt += __shfl_xor_sync(0xffffffffu, lt, off);
            p_sm[w * 32 + lane] = pv;            // transposed: [head][token]
            if (lane == 0) {
                float al = __expf(mo - mn);
                l_sm[w] = al * l_sm[w] + lt;
                m_sm[w] = mn;
                a_sm[w] = al;
            }
        }
        __syncthreads();

        // ---- phase B: y[h] = alpha*y[h] + sum_t p[t,h]*x[t] (warps 0..11) ----
        if (w < 12) {
            #pragma unroll
            for (int j = 0; j < 6; j++) {
                u64 alp = pack2(a_sm[6 * hhB + j]);
                y[j][0] = mul2(y[j][0], alp);
                y[j][1] = mul2(y[j][1], alp);
            }
            float pv[6];
            #pragma unroll
            for (int j = 0; j < 6; j++)
                pv[j] = p_sm[(6 * hhB + j) * 32 + lane];
            const char* xbase = (const char*)xsb + 8 * (cx * 64 + lane);
            #pragma unroll 2
            for (int t = 0; t < TT_; t++) {   // p==0 beyond TTl
                const char* xr = xbase + (size_t)t * (XS_STRIDE * 4);
                u64 xv0 = *(const u64*)(xr);
                u64 xv1 = *(const u64*)(xr + 8 * 32);
                #pragma unroll
                for (int j = 0; j < 6; j++) {
                    u64 pj = pack2(__shfl_sync(0xffffffffu, pv[j], t));
                    y[j][0] = fma2(pj, xv0, y[j][0]);
                    y[j][1] = fma2(pj, xv1, y[j][1]);
                }
            }
        }
        // no trailing sync: next iteration's top sync fences buffer reuse
    }

    // epilogue (no sync needed: m/l last written before the final B barrier)
    if (tid < H_) {
        g_m[b][sp][tid] = m_sm[tid];
        g_l[b][sp][tid] = l_sm[tid];
    }
    if (w < 12) {
        #pragma unroll
        for (int j = 0; j < 6; j++) {
            u64* gy = (u64*)&g_y[b][sp][6 * hhB + j][0];
            gy[cx * 64 + lane     ] = y[j][0];
            gy[cx * 64 + lane + 32] = y[j][1];
        }
    }
}

// ===================== K3: combine splits + V-proj (fused) =====================
__global__ void k_cc(const float* __restrict__ kv_w,
                     const float* __restrict__ kv_b) {
    int h = blockIdx.x, b = blockIdx.y, tid = threadIdx.x;
    int w = tid >> 5, lane = tid & 31;
    __shared__ float ws[SPLITS];
    __shared__ float linv_s;
    __shared__ float y_s[C_];

    if (tid < 32) {
        float m = (lane < SPLITS) ? g_m[b][lane][h] : -1e30f;
        float mg = m;
        #pragma unroll
        for (int off = 16; off; off >>= 1)
            mg = fmaxf(mg, __shfl_xor_sync(0xffffffffu, mg, off));
        float e = (lane < SPLITS) ? __expf(m - mg) : 0.f;
        float le = (lane < SPLITS) ? g_l[b][lane][h] * e : 0.f;
        #pragma unroll
        for (int off = 16; off; off >>= 1)
            le += __shfl_xor_sync(0xffffffffu, le, off);
        if (lane < SPLITS) ws[lane] = e;
        if (lane == 0) linv_s = 1.f / le;
    }
    __syncthreads();

    if (tid < C4_) {
        float4 acc = make_float4(0.f, 0.f, 0.f, 0.f);
        #pragma unroll
        for (int s = 0; s < SPLITS; s++) {
            float4 v = ((const float4*)&g_y[b][s][h][0])[tid];
            float wv = ws[s];
            acc.x = fmaf(wv, v.x, acc.x);
            acc.y = fmaf(wv, v.y, acc.y);
            acc.z = fmaf(wv, v.z, acc.z);
            acc.w = fmaf(wv, v.w, acc.w);
        }
        float li = linv_s;
        ((float4*)y_s)[tid] =
            make_float4(acc.x * li, acc.y * li, acc.z * li, acc.w * li);
    }
    __syncthreads();

    const float4* y4 = (const float4*)y_s;
    for (int oo = w; oo < 64; oo += 8) {
        int o = h * 64 + oo;
        const float4* kr = (const float4*)(kv_w + (size_t)(C_ + o) * C_);
        float s = 0.f;
        #pragma unroll
        for (int k = 0; k < 6; k++)
            s += dot4(kr[lane + 32*k], y4[lane + 32*k]);
        #pragma unroll
        for (int off = 16; off; off >>= 1)
            s += __shfl_xor_sync(0xffffffffu, s, off);
        if (lane == 0) g_cls[b][o] = s + kv_b[C_ + o];
    }
}

// ===================== K4: out = W_p cls + b_p =====================
__global__ void k_proj(const float* __restrict__ proj_w,
                       const float* __restrict__ proj_b,
                       float* __restrict__ out) {
    int xblk = blockIdx.x, b = blockIdx.y, tid = threadIdx.x;
    int w = tid >> 5, lane = tid & 31;
    __shared__ float c_s[C_];
    for (int i = tid; i < C_; i += 256) c_s[i] = g_cls[b][i];
    __syncthreads();
    const float4* c4 = (const float4*)c_s;
    for (int oo = w; oo < 64; oo += 8) {
        int o = xblk * 64 + oo;
        const float4* prw = (const float4*)(proj_w + (size_t)o * C_);
        float s = 0.f;
        #pragma unroll
        for (int k = 0; k < 6; k++)
            s += dot4(prw[lane + 32*k], c4[lane + 32*k]);
        #pragma unroll
        for (int off = 16; off; off >>= 1)
            s += __shfl_xor_sync(0xffffffffu, s, off);
        if (lane == 0) out[b * C_ + o] = s + proj_b[o];
    }
}

// ===================== launch =====================
extern "C" void kernel_launch(void* const* d_in, const int* in_sizes, int n_in,
                              void* d_out, int out_size) {
    const float* x      = (const float*)d_in[0];
    const float* kv_w   = (const float*)d_in[1];
    const float* kv_b   = (const float*)d_in[2];
    const float* q_w    = (const float*)d_in[3];
    const float* q_b    = (const float*)d_in[4];
    const float* proj_w = (const float*)d_in[5];
    const float* proj_b = (const float*)d_in[6];
    float* out = (float*)d_out;

    size_t smem = (size_t)(2 * TT_ * XS_STRIDE + H_ * C_ + H_ * 8 * 32
                           + H_ * 32 + 3 * H_) * sizeof(float);  // 223,760 B
    cudaFuncSetAttribute(k_attn, cudaFuncAttributeMaxDynamicSharedMemorySize,
                         (int)smem);

    k_qs   <<<dim3(H_, B_), 256>>>(x, q_w, q_b, kv_w);       // launch 1
    k_attn <<<dim3(SPLITS, B_), K2_THREADS, smem>>>(x);      // launch 2 (ncu target)
    k_cc   <<<dim3(H_, B_), 256>>>(kv_w, kv_b);              // launch 3
    k_proj <<<dim3(H_, B_), 256>>>(proj_w, proj_b, out);     // launch 4
}